// round 16
// baseline (speedup 1.0000x reference)
#include <cuda_runtime.h>
#include <cstdint>

// ---------------- problem constants ----------------
#define B_   1024
#define S_   200
#define D_   64
#define NI_  4
#define E_   256            // NI * D
#define INTEREST_ELEMS (B_ * NI_ * D_)   // 262144, adj follows at this offset

// ---------------- device scratch (static; no runtime alloc) ----------------
__device__ float g_uprof[B_ * D_];                       // 256 KB
__device__ float g_item[(long long)B_ * S_ * D_];        // 52.4 MB
__device__ float g_hat [(long long)S_ * B_ * E_];        // 209.7 MB, [s][rank][e]
__device__ int   g_cnt [S_];                             // active-b count per s
__device__ int   g_blist[S_ * B_];                       // [s][rank] -> b
__device__ int   g_rank [S_ * B_];                       // [s][b] -> rank

// ---------------- cp.async / cluster helpers ----------------
#define CP_ASYNC16(dst_u32, src_ptr) \
    asm volatile("cp.async.cg.shared.global [%0], [%1], 16;" \
                 :: "r"(dst_u32), "l"(src_ptr))
#define CP_COMMIT() \
    asm volatile("cp.async.commit_group;" ::: "memory")
#define CP_WAIT_GROUP(n) \
    asm volatile("cp.async.wait_group %0;" :: "n"(n) : "memory")

#define CLUSTER_SYNC() do { \
    asm volatile("barrier.cluster.arrive.aligned;" ::: "memory"); \
    asm volatile("barrier.cluster.wait.aligned;" ::: "memory"); \
} while (0)

// store val to the SAME smem offset in peer CTA of the cluster
#define ST_CLUSTER_F32(addr_u32, peer, val) \
    asm volatile("{\n\t.reg .b32 r;\n\t" \
                 "mapa.shared::cluster.u32 r, %0, %1;\n\t" \
                 "st.shared::cluster.f32 [r], %2;\n\t}" \
                 :: "r"(addr_u32), "r"(peer), "f"(val) : "memory")

__device__ __forceinline__ uint32_t ctarank() {
    uint32_t r;
    asm("mov.u32 %0, %%cluster_ctarank;" : "=r"(r));
    return r;
}

// ---------------- tf32 mma helpers ----------------
__device__ __forceinline__ uint32_t f2tf(float x) {
    uint32_t u;
    asm("cvt.rna.tf32.f32 %0, %1;" : "=r"(u) : "f"(x));
    return u;
}

__device__ __forceinline__ void mma8(float* d, const uint32_t* a,
                                     uint32_t b0, uint32_t b1) {
    asm volatile(
        "mma.sync.aligned.m16n8k8.row.col.f32.tf32.tf32.f32 "
        "{%0,%1,%2,%3}, {%4,%5,%6,%7}, {%8,%9}, {%0,%1,%2,%3};"
        : "+f"(d[0]), "+f"(d[1]), "+f"(d[2]), "+f"(d[3])
        : "r"(a[0]), "r"(a[1]), "r"(a[2]), "r"(a[3]), "r"(b0), "r"(b1));
}

#define LDA 68     // smem row stride (uint32); conflict-free fragment LDS
#define SMEM_GEMM_BYTES (2 * 128 * LDA * 4)   // 69632

// 128x128x64 block tile, 8 warps of 32x64 each.
__device__ __forceinline__ void mma_core(const uint32_t* __restrict__ As,
                                         const uint32_t* __restrict__ Bs,
                                         int tid, float acc[2][8][4]) {
    const int lane = tid & 31, wid = tid >> 5;
    const int g = lane >> 2, t = lane & 3;
    const int m0 = (wid & 3) * 32, n0 = (wid >> 2) * 64;
    #pragma unroll
    for (int k0 = 0; k0 < 64; k0 += 8) {
        uint32_t a[2][4];
        #pragma unroll
        for (int mf = 0; mf < 2; ++mf) {
            const uint32_t* p = As + (m0 + 16 * mf + g) * LDA + k0 + t;
            a[mf][0] = p[0];
            a[mf][1] = p[8 * LDA];
            a[mf][2] = p[4];
            a[mf][3] = p[8 * LDA + 4];
        }
        #pragma unroll
        for (int nf = 0; nf < 8; ++nf) {
            const uint32_t* p = Bs + (n0 + 8 * nf + g) * LDA + k0 + t;
            uint32_t b0v = p[0], b1v = p[4];
            mma8(acc[0][nf], a[0], b0v, b1v);
            mma8(acc[1][nf], a[1], b0v, b1v);
        }
    }
}

// ====================================================================
// K0: zero the per-s active counters (gather's only ordering need)
// ====================================================================
__global__ void zcnt_kernel() {
    if (threadIdx.x < S_) g_cnt[threadIdx.x] = 0;
}

// ====================================================================
// K1: user profile
// ====================================================================
__global__ __launch_bounds__(256) void uprof_kernel(
    const int* __restrict__ uid, const int* __restrict__ age,
    const int* __restrict__ gender, const int* __restrict__ occup,
    const float* __restrict__ ue, const float* __restrict__ at,
    const float* __restrict__ gt, const float* __restrict__ ot)
{
    int idx = blockIdx.x * 256 + threadIdx.x;
    int b = idx >> 6, d = idx & 63;
    float v = ue[(size_t)uid[b]    * 64 + d]
            + gt[(size_t)gender[b] * 64 + d]
            + at[(size_t)age[b]    * 64 + d]
            + ot[(size_t)occup[b]  * 64 + d];
    g_uprof[idx] = 0.25f * v;
}

// ====================================================================
// K2: item_his = mid_emb[mid_his]*mask  (+ build per-s active-b lists)
// ====================================================================
__global__ __launch_bounds__(256) void gather_kernel(
    const int* __restrict__ mid_his, const float* __restrict__ mask,
    const float* __restrict__ mid_emb)
{
    int t  = blockIdx.x * 256 + threadIdx.x;
    int bs = t >> 4, q = t & 15;
    int mi = mid_his[bs];
    float m = mask[bs];
    float4 e = ((const float4*)mid_emb)[(size_t)mi * 16 + q];
    float4 it;
    it.x = e.x * m;  it.y = e.y * m;  it.z = e.z * m;  it.w = e.w * m;
    ((float4*)g_item)[(size_t)bs * 16 + q] = it;

    if (q == 0 && m != 0.f) {
        int b = bs / S_, s = bs - b * S_;
        int r = atomicAdd(&g_cnt[s], 1);
        g_blist[s * B_ + r] = b;
        g_rank [s * B_ + b] = r;
    }
}

// ====================================================================
// K3: adj — tf32 tensor cores, ROW-COMPACTED (active i only)
// ====================================================================
__global__ __launch_bounds__(256) void adj_kernel(
    const float* __restrict__ mask, float* __restrict__ out)
{
    extern __shared__ uint32_t sh[];
    uint32_t* As = sh;
    uint32_t* Bs = sh + 128 * LDA;
    __shared__ float msk[256];
    __shared__ int act[S_], inact[S_];
    __shared__ int wtotA[8], wtotI[8];
    __shared__ int nact_s;

    const int b  = blockIdx.z;
    const int i0 = blockIdx.y * 128;       // compacted-row tile origin
    const int j0 = blockIdx.x * 128;
    const int tid = threadIdx.x;
    const int lane = tid & 31, wrp = tid >> 5;
    const float* It = g_item + (size_t)b * (S_ * D_);
    float* outb = out + (size_t)b * (S_ * S_);

    float mval = (tid < S_) ? mask[b * S_ + tid] : 0.f;
    msk[tid] = mval;

    int predA = (tid < S_) && (mval != 0.f);
    int predI = (tid < S_) && (mval == 0.f);
    unsigned balA = __ballot_sync(0xffffffffu, predA);
    unsigned balI = __ballot_sync(0xffffffffu, predI);
    if (lane == 0) { wtotA[wrp] = __popc(balA); wtotI[wrp] = __popc(balI); }
    __syncthreads();
    int pA = 0, pI = 0;
    for (int i = 0; i < wrp; ++i) { pA += wtotA[i]; pI += wtotI[i]; }
    unsigned ltm = (1u << lane) - 1u;
    if (predA) act[pA + __popc(balA & ltm)] = tid;
    if (predI) inact[pI + __popc(balI & ltm)] = tid;
    if (tid == 0) {
        int t = 0;
        for (int i = 0; i < 7; ++i) t += wtotA[i];
        nact_s = t;
    }
    __syncthreads();
    const int nact = nact_s;

    if (blockIdx.y == 1) {
        int ninact = S_ - nact;
        int jw = (j0 + 128 <= S_) ? 128 : (S_ - j0);
        int nf4 = jw >> 2;
        for (int x = tid; x < ninact * nf4; x += 256) {
            int r = x / nf4, c4 = x - r * nf4;
            *(float4*)(outb + (size_t)inact[r] * S_ + j0 + c4 * 4) =
                make_float4(0.f, 0.f, 0.f, 0.f);
        }
    }
    if (i0 >= nact) return;

    #pragma unroll
    for (int p = 0; p < 8; ++p) {
        int q = tid + p * 256;
        int r = q >> 4, c4 = q & 15;
        float4 up = ((const float4*)g_uprof)[b * 16 + c4];
        float4 av = make_float4(0.f, 0.f, 0.f, 0.f);
        float4 bv = make_float4(0.f, 0.f, 0.f, 0.f);
        if (i0 + r < nact) {
            float4 iv = *(const float4*)(It + (size_t)act[i0 + r] * 64 + c4 * 4);
            av.x = iv.x * up.x; av.y = iv.y * up.y;
            av.z = iv.z * up.z; av.w = iv.w * up.w;
        }
        if (j0 + r < S_) bv = *(const float4*)(It + (size_t)(j0 + r) * 64 + c4 * 4);
        uint4 at4 = make_uint4(f2tf(av.x), f2tf(av.y), f2tf(av.z), f2tf(av.w));
        uint4 bt4 = make_uint4(f2tf(bv.x), f2tf(bv.y), f2tf(bv.z), f2tf(bv.w));
        *(uint4*)(As + r * LDA + c4 * 4) = at4;
        *(uint4*)(Bs + r * LDA + c4 * 4) = bt4;
    }
    __syncthreads();

    float acc[2][8][4] = {};
    mma_core(As, Bs, tid, acc);

    const int g = lane >> 2, t = lane & 3;
    const int wid = tid >> 5;
    const int m0 = (wid & 3) * 32, n0 = (wid >> 2) * 64;

    #pragma unroll
    for (int mf = 0; mf < 2; ++mf) {
        #pragma unroll
        for (int nf = 0; nf < 8; ++nf) {
            int ci = i0 + m0 + 16 * mf + g;
            int j  = j0 + n0 + 8 * nf + 2 * t;
            if (j < S_) {
                float mj0 = msk[j], mj1 = msk[j + 1];
                if (ci < nact) {
                    int i = act[ci];
                    float s0 = 1.f / (1.f + __expf(-acc[mf][nf][0]));
                    float s1 = 1.f / (1.f + __expf(-acc[mf][nf][1]));
                    *(float2*)(outb + (size_t)i * S_ + j) =
                        make_float2(s0 * mj0, s1 * mj1);
                }
                if (ci + 8 < nact) {
                    int i = act[ci + 8];
                    float s2 = 1.f / (1.f + __expf(-acc[mf][nf][2]));
                    float s3 = 1.f / (1.f + __expf(-acc[mf][nf][3]));
                    *(float2*)(outb + (size_t)i * S_ + j) =
                        make_float2(s2 * mj0, s3 * mj1);
                }
            }
        }
    }
}

// ====================================================================
// K4: hat — tf32 tensor cores, ACTIVE b-rows only, compacted output.
// ====================================================================
__global__ __launch_bounds__(256) void hat_kernel(const float* __restrict__ w)
{
    const int s   = blockIdx.z;
    const int cnt = g_cnt[s];
    const int b0  = blockIdx.y * 128;
    if (b0 >= cnt) return;
    const int e0  = blockIdx.x * 128;
    const int tid = threadIdx.x;

    extern __shared__ uint32_t sh[];
    uint32_t* As = sh;
    uint32_t* Bs = sh + 128 * LDA;

    #pragma unroll
    for (int p = 0; p < 8; ++p) {
        int q = tid + p * 256;
        int r = q >> 4, c4 = q & 15;
        float4 av = make_float4(0.f, 0.f, 0.f, 0.f);
        if (b0 + r < cnt) {
            int bidx = g_blist[s * B_ + b0 + r];
            av = *(const float4*)(g_item + ((size_t)bidx * S_ + s) * 64 + c4 * 4);
        }
        float4 bv = *(const float4*)(w + ((size_t)s * E_ + (e0 + r)) * 64 + c4 * 4);
        uint4 at4 = make_uint4(f2tf(av.x), f2tf(av.y), f2tf(av.z), f2tf(av.w));
        uint4 bt4 = make_uint4(f2tf(bv.x), f2tf(bv.y), f2tf(bv.z), f2tf(bv.w));
        *(uint4*)(As + r * LDA + c4 * 4) = at4;
        *(uint4*)(Bs + r * LDA + c4 * 4) = bt4;
    }
    __syncthreads();

    float acc[2][8][4] = {};
    mma_core(As, Bs, tid, acc);

    const int lane = tid & 31, wid = tid >> 5;
    const int g = lane >> 2, t = lane & 3;
    const int m0 = (wid & 3) * 32, n0 = (wid >> 2) * 64;

    #pragma unroll
    for (int mf = 0; mf < 2; ++mf) {
        #pragma unroll
        for (int nf = 0; nf < 8; ++nf) {
            int ri = b0 + m0 + 16 * mf + g;
            int e  = e0 + n0 + 8 * nf + 2 * t;
            if (ri < cnt)
                *(float2*)(g_hat + ((size_t)s * B_ + ri) * E_ + e) =
                    make_float2(acc[mf][nf][0], acc[mf][nf][1]);
            if (ri + 8 < cnt)
                *(float2*)(g_hat + ((size_t)s * B_ + ri + 8) * E_ + e) =
                    make_float2(acc[mf][nf][2], acc[mf][nf][3]);
        }
    }
}

// ====================================================================
// K5: routing, 2-CTA cluster c-split; staged cp.async load fused with
//     iteration 0 (cw=0 -> sw=0.25 exactly, so v0 = 0.25 * row-sum,
//     accumulated per commit-group as data arrives).
// ====================================================================
#define HPAD 260          // floats per smem row (1040 B)
#define HN_MAX 100        // worst-case rows per CTA (ceil(200/2))
#define ROUTE_SMEM (HN_MAX * HPAD * 4)   // 104000 B
#define RT_THREADS 512
__global__ __launch_bounds__(RT_THREADS) __cluster_dims__(2, 1, 1)
void route_kernel(const float* __restrict__ mask,
                  float* __restrict__ out_interest)
{
    extern __shared__ float hat_s[];                 // [cn][260]
    __shared__ float cw_s[NI_ * HN_MAX];
    __shared__ float sw_s[NI_ * HN_MAX];
    __shared__ float cap_s[E_];
    __shared__ float vbuf[3][E_];                    // per-iter exchange slots
    __shared__ float wsum[16];
    __shared__ int   act[S_];
    __shared__ int   act_row[S_];
    __shared__ int   wtot[16];
    __shared__ int   nact_s;

    const int b = blockIdx.x >> 1;
    const uint32_t rank = ctarank();
    const uint32_t peer = rank ^ 1u;
    const int tid = threadIdx.x;
    const int lane = tid & 31, wrp = tid >> 5;

    // ---- deterministic compaction of active s (mask != 0) ----
    int pred = (tid < S_) ? (mask[b * S_ + tid] != 0.f) : 0;
    unsigned bal = __ballot_sync(0xffffffffu, pred);
    if (lane == 0) wtot[wrp] = __popc(bal);
    __syncthreads();
    int prefix = 0;
    for (int i = 0; i < wrp && i < 7; ++i) prefix += wtot[i];
    if (pred) act[prefix + __popc(bal & ((1u << lane) - 1u))] = tid;
    if (tid == 0) {
        int t = 0;
        for (int i = 0; i < 7; ++i) t += wtot[i];
        nact_s = t;
    }
    __syncthreads();
    const int nact = nact_s;
    const int hn = (nact + 1) >> 1;                  // rows per rank
    const int cbase = (int)rank * hn;
    const int cn = (cbase + hn <= nact) ? hn : (nact - cbase);  // my rows

    // ---- resolve compacted global row index ----
    if (tid < nact) {
        int s = act[tid];
        act_row[tid] = s * B_ + g_rank[s * B_ + b];
    }
    for (int x = tid; x < NI_ * HN_MAX; x += RT_THREADS) cw_s[x] = 0.f;
    __syncthreads();

    const int k = tid >> 7;           // 0..3
    const int d = (tid >> 1) & 63;    // pair shares (k,d)
    const int half = tid & 1;
    const int off = k * 64 + d;
    const int g8 = lane >> 2, q4 = lane & 3;     // cw-update layout
    const uint32_t vbuf_sh = (uint32_t)__cvta_generic_to_shared(vbuf);

    // ---- staged load: 4 commit groups of rows ----
    uint32_t smem_b = (uint32_t)__cvta_generic_to_shared(hat_s);
    const int ck = (cn + 3) >> 2;                    // rows per chunk
    #pragma unroll
    for (int gch = 0; gch < 4; ++gch) {
        int r0 = gch * ck;
        int r1 = (r0 + ck < cn) ? r0 + ck : cn;
        int n4 = (r1 - r0) * 64;
        for (int x4 = tid; x4 < n4; x4 += RT_THREADS) {
            int c = r0 + (x4 >> 6), e4 = (x4 & 63) << 2;
            const float* src = g_hat + ((size_t)act_row[cbase + c] << 8) + e4;
            CP_ASYNC16(smem_b + (uint32_t)(c * HPAD + e4) * 4, src);
        }
        CP_COMMIT();
    }

    // ---- iteration 0 v-pass fused with arrival (sw == 0.25 exactly) ----
    float v = 0.f;
    {
        int r0 = 0, r1 = (ck < cn) ? ck : cn;
        CP_WAIT_GROUP(3);
        __syncthreads();
        for (int c = r0 + half; c < r1; c += 2) v += hat_s[c * HPAD + off];
        r0 = r1; r1 = (2 * ck < cn) ? 2 * ck : cn;
        CP_WAIT_GROUP(2);
        __syncthreads();
        for (int c = r0 + half; c < r1; c += 2) v += hat_s[c * HPAD + off];
        r0 = r1; r1 = (3 * ck < cn) ? 3 * ck : cn;
        CP_WAIT_GROUP(1);
        __syncthreads();
        for (int c = r0 + half; c < r1; c += 2) v += hat_s[c * HPAD + off];
        r0 = r1;
        CP_WAIT_GROUP(0);
        __syncthreads();
        for (int c = r0 + half; c < cn; c += 2) v += hat_s[c * HPAD + off];
        v *= 0.25f;
        v += __shfl_xor_sync(0xffffffffu, v, 1);     // my-CTA partial
    }

    float capv = 0.f;
    for (int it = 0; it < 3; ++it) {
        if (it > 0) {
            // softmax over k at my active positions
            if (tid < cn) {
                float c0 = cw_s[0 * HN_MAX + tid], c1 = cw_s[1 * HN_MAX + tid];
                float c2 = cw_s[2 * HN_MAX + tid], c3 = cw_s[3 * HN_MAX + tid];
                float mx = fmaxf(fmaxf(c0, c1), fmaxf(c2, c3));
                float e0 = __expf(c0 - mx), e1 = __expf(c1 - mx);
                float e2 = __expf(c2 - mx), e3 = __expf(c3 - mx);
                float inv = 1.0f / (e0 + e1 + e2 + e3);
                sw_s[0 * HN_MAX + tid] = e0 * inv;
                sw_s[1 * HN_MAX + tid] = e1 * inv;
                sw_s[2 * HN_MAX + tid] = e2 * inv;
                sw_s[3 * HN_MAX + tid] = e3 * inv;
            }
            __syncthreads();

            // v[k,d] partial over my rows; pair-split then shfl
            v = 0.f;
            const float* swk = &sw_s[k * HN_MAX];
            const int pn = (cn + 1) >> 1;
            const int cbeg = half * pn;
            const int cend = (cbeg + pn < cn) ? cbeg + pn : cn;
            #pragma unroll 4
            for (int c = cbeg; c < cend; ++c)
                v += swk[c] * hat_s[c * HPAD + off];
            v += __shfl_xor_sync(0xffffffffu, v, 1);
        }

        // exchange partials via peer smem; one cluster barrier
        if (!half)
            ST_CLUSTER_F32(vbuf_sh + (uint32_t)(it * E_ + off) * 4, peer, v);
        CLUSTER_SYNC();
        float vf = v + vbuf[it][off];                // full v[k,d]

        // squash (computed redundantly in both CTAs)
        float p = half ? 0.f : vf * vf;
        #pragma unroll
        for (int o = 16; o; o >>= 1) p += __shfl_xor_sync(0xffffffffu, p, o);
        if (lane == 0) wsum[wrp] = p;
        __syncthreads();
        float n = wsum[4 * k] + wsum[4 * k + 1] + wsum[4 * k + 2] + wsum[4 * k + 3];
        float scale = n / (1.0f + n) / sqrtf(n + 1e-9f);
        capv = scale * vf;
        if (!half) cap_s[off] = capv;
        __syncthreads();

        if (it < 2) {
            // cw[kk,c] += hat[c, kk*64:] . cap[kk,:]  (my rows only)
            // 4 lanes per dot: banks 4g8+q4 distinct -> conflict-free.
            const int ndots = NI_ * cn;
            for (int j0 = wrp * 8; j0 < ndots; j0 += 16 * 8) {
                int j = j0 + g8;
                float p2 = 0.f;
                int kk = 0, c = 0;
                if (j < ndots) {
                    kk = j / cn; c = j - kk * cn;
                    const float* hr = &hat_s[c * HPAD + kk * 64 + q4];
                    const float* cr = &cap_s[kk * 64 + q4];
                    #pragma unroll
                    for (int i = 0; i < 16; ++i)
                        p2 += hr[4 * i] * cr[4 * i];
                }
                p2 += __shfl_xor_sync(0xffffffffu, p2, 1);
                p2 += __shfl_xor_sync(0xffffffffu, p2, 2);
                if (j < ndots && q4 == 0) cw_s[kk * HN_MAX + c] += p2;
            }
            __syncthreads();
        }
    }

    if (rank == 0 && !half) out_interest[(size_t)b * E_ + off] = capv;
}

// ====================================================================
// launch — capture-legal fork: root event on origin stream first, then
//          uprof on s2 || zcnt+gather on origin; hat->route on s2
//          (high priority); adj overlaps on origin.
// ====================================================================
extern "C" void kernel_launch(void* const* d_in, const int* in_sizes, int n_in,
                              void* d_out, int out_size)
{
    const int*   uid      = (const int*)  d_in[0];
    const int*   age      = (const int*)  d_in[1];
    const int*   gender   = (const int*)  d_in[2];
    const int*   occup    = (const int*)  d_in[3];
    const int*   mid_his  = (const int*)  d_in[4];
    const float* mask     = (const float*)d_in[5];
    const float* ue       = (const float*)d_in[6];
    const float* at       = (const float*)d_in[7];
    const float* gt       = (const float*)d_in[8];
    const float* ot       = (const float*)d_in[9];
    const float* mid_emb  = (const float*)d_in[10];
    const float* w        = (const float*)d_in[11];
    float* out = (float*)d_out;

    static cudaStream_t s2 = nullptr;
    static cudaEvent_t ev_root = nullptr, ev_fork = nullptr,
                       ev_join = nullptr, ev_uprof = nullptr;
    if (!s2) {
        int lo, hi;
        cudaDeviceGetStreamPriorityRange(&lo, &hi);
        cudaStreamCreateWithPriority(&s2, cudaStreamNonBlocking, hi);
        cudaEventCreateWithFlags(&ev_root, cudaEventDisableTiming);
        cudaEventCreateWithFlags(&ev_fork, cudaEventDisableTiming);
        cudaEventCreateWithFlags(&ev_join, cudaEventDisableTiming);
        cudaEventCreateWithFlags(&ev_uprof, cudaEventDisableTiming);
        cudaFuncSetAttribute(route_kernel,
                             cudaFuncAttributeMaxDynamicSharedMemorySize, ROUTE_SMEM);
        cudaFuncSetAttribute(adj_kernel,
                             cudaFuncAttributeMaxDynamicSharedMemorySize, SMEM_GEMM_BYTES);
        cudaFuncSetAttribute(hat_kernel,
                             cudaFuncAttributeMaxDynamicSharedMemorySize, SMEM_GEMM_BYTES);
    }

    // capture-legal fork of s2 from the origin stream
    cudaEventRecord(ev_root, 0);
    cudaStreamWaitEvent(s2, ev_root, 0);

    // uprof on s2 concurrently with zcnt+gather on the origin stream
    uprof_kernel<<<B_ * D_ / 256, 256, 0, s2>>>(uid, age, gender, occup,
                                                ue, at, gt, ot);
    cudaEventRecord(ev_uprof, s2);

    zcnt_kernel<<<1, 256>>>();
    gather_kernel<<<B_ * S_ * 16 / 256, 256>>>(mid_his, mask, mid_emb);
    cudaEventRecord(ev_fork, 0);

    cudaStreamWaitEvent(s2, ev_fork, 0);
    hat_kernel<<<dim3(2, B_ / 128, S_), 256, SMEM_GEMM_BYTES, s2>>>(w);
    route_kernel<<<2 * B_, RT_THREADS, ROUTE_SMEM, s2>>>(mask, out);

    cudaStreamWaitEvent(0, ev_uprof, 0);
    adj_kernel<<<dim3(2, 2, B_), 256, SMEM_GEMM_BYTES>>>(mask, out + INTEREST_ELEMS);

    cudaEventRecord(ev_join, s2);
    cudaStreamWaitEvent(0, ev_join, 0);
}